// round 13
// baseline (speedup 1.0000x reference)
#include <cuda_runtime.h>
#include <cstdint>

#define B_     16
#define T_     65536
#define CHUNKS 128
#define TILE   256
#define NTIL   2
#define L_     512
#define PBN    76
#define HH     4096
#define TFL    (TILE * 64)          // floats per tile
typedef unsigned long long ull;
typedef unsigned int u32;

__device__ float g_u [(size_t)B_ * T_ * 64];
__device__ float g_bu[(size_t)B_ * T_ * 64];
__device__ float g_ends[B_ * CHUNKS * 64];
__device__ float g_carr[B_ * CHUNKS * 64];
__device__ float g_cX[64];
__device__ float g_wlo[64];
__device__ float g_aux[1];
__device__ float g_wT[12 * HH];   // fragment-packed tf32 weights

__device__ __forceinline__ void fma2(ull& d, ull a, ull b) {
    asm("fma.rn.f32x2 %0, %1, %2, %0;" : "+l"(d) : "l"(a), "l"(b));
}
__device__ __forceinline__ ull add2(ull a, ull b) {
    ull d; asm("add.rn.f32x2 %0, %1, %2;" : "=l"(d) : "l"(a), "l"(b)); return d;
}
__device__ __forceinline__ ull mul2(ull a, ull b) {
    ull d; asm("mul.rn.f32x2 %0, %1, %2;" : "=l"(d) : "l"(a), "l"(b)); return d;
}
__device__ __forceinline__ ull dup2(float x) {
    ull r; asm("mov.b64 %0, {%1, %1};" : "=l"(r) : "f"(x)); return r;
}
__device__ __forceinline__ float2 unp(ull p) {
    float2 r; asm("mov.b64 {%0, %1}, %2;" : "=f"(r.x), "=f"(r.y) : "l"(p)); return r;
}
__device__ __forceinline__ ull pk(float a, float b) {
    ull r; asm("mov.b64 %0, {%1, %2};" : "=l"(r) : "f"(a), "f"(b)); return r;
}
__device__ __forceinline__ u32 cvt_tf32(float x) {
    u32 r; asm("cvt.rna.tf32.f32 %0, %1;" : "=r"(r) : "f"(x)); return r;
}
__device__ __forceinline__ void mma_tf32(float* d, u32 a0, u32 a1, u32 a2,
                                         u32 a3, u32 b0, u32 b1) {
    asm volatile(
        "mma.sync.aligned.m16n8k8.row.col.f32.tf32.tf32.f32 "
        "{%0,%1,%2,%3}, {%4,%5,%6,%7}, {%8,%9}, {%0,%1,%2,%3};"
        : "+f"(d[0]), "+f"(d[1]), "+f"(d[2]), "+f"(d[3])
        : "r"(a0), "r"(a1), "r"(a2), "r"(a3), "r"(b0), "r"(b1));
}

__device__ __forceinline__ void stage16k(u32 dst, const float* __restrict__ src,
                                         int tid) {
#pragma unroll
    for (int j = 0; j < 8; j++) {
        asm volatile("cp.async.ca.shared.global [%0], [%1], 16;"
                     :: "r"(dst + tid * 16 + j * 2048),
                        "l"(src + tid * 4 + j * 512));
    }
    asm volatile("cp.async.commit_group;");
}
__device__ __forceinline__ void cpwait() {
    asm volatile("cp.async.wait_group 0;");
}

// fragment-layout gmem offset: warp w owns 64 rows; j = nt*4 + mt (0..31)
__device__ __forceinline__ size_t fragoff(size_t toff, int w, int j, int lane) {
    return toff + (size_t)w * 4096 + (size_t)(j * 32 + lane) * 4;
}

// m64n64k64 warp GEMM: out[t][n] = sum_k BUF[t][k] * M[n][k].
__device__ __forceinline__ void gemm_mma(const float* __restrict__ BUF,
                                         const float* __restrict__ wt,
                                         int rb0, int lq, int kcol, int lane,
                                         float acc[8][16]) {
#pragma unroll
    for (int s = 0; s < 8; s++) {
        const int kb = s * 8;
        u32 a[4][4];
#pragma unroll
        for (int mt = 0; mt < 4; mt++) {
            const float* p = BUF + (rb0 + 16 * mt + lq) * PBN + kb + kcol;
            a[mt][0] = cvt_tf32(p[0]);
            a[mt][1] = cvt_tf32(p[8 * PBN]);
            a[mt][2] = cvt_tf32(p[4]);
            a[mt][3] = cvt_tf32(p[8 * PBN + 4]);
        }
        const uint2* wp = (const uint2*)(wt + s * 512) + lane;
#pragma unroll
        for (int nt = 0; nt < 8; nt++) {
            uint2 b = wp[nt * 32];
#pragma unroll
            for (int mt = 0; mt < 4; mt++)
                mma_tf32(&acc[nt][4 * mt], a[mt][0], a[mt][1], a[mt][2],
                         a[mt][3], b.x, b.y);
        }
    }
}

// store D fragments into BUF [t][n]
__device__ __forceinline__ void stile_mma(float* __restrict__ BUF, int rb0,
                                          int lq, int kcol,
                                          const float acc[8][16]) {
#pragma unroll
    for (int nt = 0; nt < 8; nt++) {
        const int nc = nt * 8 + 2 * kcol;
#pragma unroll
        for (int mt = 0; mt < 4; mt++) {
            const int r0 = rb0 + 16 * mt + lq;
            *(ull*)(BUF + r0 * PBN + nc) = pk(acc[nt][4 * mt], acc[nt][4 * mt + 1]);
            *(ull*)(BUF + (r0 + 8) * PBN + nc) =
                pk(acc[nt][4 * mt + 2], acc[nt][4 * mt + 3]);
        }
    }
}

// ---------------------------------------------------------------------------
__global__ void __launch_bounds__(128)
k_prep(const float* __restrict__ Cm, const float* __restrict__ Wl,
       const float* __restrict__ Bm, const float* __restrict__ ga,
       const float* __restrict__ Win, const float* __restrict__ bl,
       const float* __restrict__ Wout) {
    const int b = blockIdx.x;
    const int tid = threadIdx.x;
    if (b == 12) {
        if (tid < 64) {
            const int n = tid;
            float a = 0.f;
#pragma unroll
            for (int k = 0; k < 64; k++) a = fmaf(Bm[n * 64 + k], Win[k], a);
            g_cX[n] = expf(ga[n]) * a;
            float w = 0.f;
#pragma unroll
            for (int j = 0; j < 64; j++)
                w = fmaf(Wout[j], Wl[3 * HH + j * 64 + n], w);
            g_wlo[n] = w;
            if (n == 0) {
                float s = 0.f;
#pragma unroll
                for (int j = 0; j < 64; j++) s = fmaf(Wout[j], bl[192 + j], s);
                g_aux[0] = s;
            }
        }
        return;
    }
    const int l = b / 3, m = b % 3;
    if (m == 2 && l == 3) return;
    __shared__ float gam[64];
    const float* src = (m == 0) ? Cm + l * HH
                     : (m == 1) ? Wl + l * HH
                                : Bm + (l + 1) * HH;
    u32* dst = (u32*)(g_wT + b * HH);
    if (m == 2) {
        if (tid < 64) gam[tid] = expf(ga[(l + 1) * 64 + tid]);
        __syncthreads();
    }
    for (int idx = tid; idx < HH; idx += 128) {
        const int c = idx & 1, ln = (idx >> 1) & 31;
        const int nt = (idx >> 6) & 7, s = idx >> 9;
        const int n = nt * 8 + (ln >> 2);
        const int k = s * 8 + (ln & 3) + 4 * c;
        float v = src[n * 64 + k];
        if (m == 2) v *= gam[n];
        dst[idx] = cvt_tf32(v);
    }
}

__global__ void __launch_bounds__(128)
k_init(const float* __restrict__ x, float* __restrict__ ends,
       const float* __restrict__ nu_log) {
    __shared__ __align__(16) float xs[128];
    const int tid = threadIdx.x;
    const int bc = blockIdx.x;
    const long tokbase = (long)(bc / CHUNKS) * T_ + (long)(bc % CHUNKS) * L_;

    float A = 0.f, a4 = 0.f, s = 0.f;
    if (tid < 64) {
        A = expf(-expf(nu_log[tid]));
        float a2 = A * A; a4 = a2 * a2;
    }
    for (int tl = 0; tl < 4; tl++) {
        __syncthreads();
        xs[tid] = x[tokbase + tl * 128 + tid];
        __syncthreads();
        if (tid < 64) {
#pragma unroll 8
            for (int q = 0; q < 32; q++) {
                float4 v = *(const float4*)(xs + 4 * q);
                float p2 = fmaf(A, v.x, v.y);
                float p3 = fmaf(A, p2, v.z);
                float p4 = fmaf(A, p3, v.w);
                s = fmaf(a4, s, p4);
            }
        }
    }
    if (tid < 64) ends[bc * 64 + tid] = g_cX[tid] * s;
}

__global__ void __launch_bounds__(128)
k_combine(const float* __restrict__ ends, float* __restrict__ carries,
          const float* __restrict__ nu_log) {
    __shared__ float es[CHUNKS * 64];
    const int b = blockIdx.x;
    const int tid = threadIdx.x;
    for (int i = tid; i < CHUNKS * 64; i += 128)
        es[i] = ends[b * CHUNKS * 64 + i];
    __syncthreads();
    if (tid < 64) {
        const int n = tid;
        const float AL = expf(-expf(nu_log[n]) * (float)L_);
        float carry = 0.f;
#pragma unroll 8
        for (int c = 0; c < CHUNKS; c++) {
            carries[(b * CHUNKS + c) * 64 + n] = carry;
            carry = fmaf(AL, carry, es[c * 64 + n]);
        }
    }
}

// ---------------------------------------------------------------------------
// Fused per-layer kernel: m64 warps (TILE=256), 2 CTAs/SM.
// ---------------------------------------------------------------------------
#define SM_BUF  0
#define SM_W    19456         // 2 slots x 4096 floats
#define SM_XS   27648         // 256
#define SM_DV   27904
#define SM_BL   27968
#define SM_W2   28032
#define SM_WLO  28096
#define SM_AUX  28160
#define SM_CX   28164
#define SMEMF   28232
#define SMEMB   (SMEMF * 4)

template <int MODE, int REV>
__global__ void __launch_bounds__(128, 2)
k_apply(const float* __restrict__ xin, const float* __restrict__ uin,
        float* __restrict__ uout, float* __restrict__ bu,
        const float* __restrict__ carr, float* __restrict__ ends,
        const float* __restrict__ wtC, const float* __restrict__ wtW,
        const float* __restrict__ wtB,
        const float* __restrict__ Dv, const float* __restrict__ bl,
        const float* __restrict__ nu_log, const float* __restrict__ Win,
        const float* __restrict__ Wout, const float* __restrict__ nu_nx) {
    extern __shared__ __align__(16) float sm[];
    float* BUF = sm + SM_BUF;
    float* WSL = sm + SM_W;
    float* XS  = sm + SM_XS;
    float* DVs = sm + SM_DV;
    float* BLs = sm + SM_BL;
    float* W2s = sm + SM_W2;
    float* WLO = sm + SM_WLO;
    float* AUX = sm + SM_AUX;
    float* CXs = sm + SM_CX;

    const int tid = threadIdx.x;
    const int lane = tid & 31;
    const int lq = lane >> 2, kcol = lane & 3;
    const int w = tid >> 5;
    const int rb0 = w * 64;
    const int bc = REV ? (int)(gridDim.x - 1 - blockIdx.x) : (int)blockIdx.x;
    const long tokbase = (long)(bc / CHUNKS) * T_ + (long)(bc % CHUNKS) * L_;
    const u32 wS0 = (u32)__cvta_generic_to_shared(WSL);

    stage16k(wS0, wtC, tid);
    int cur = 0;

    if (tid < 64) {
        DVs[tid] = Dv[tid];
        BLs[tid] = bl[tid];
        W2s[tid] = (MODE == 0) ? Win[tid] : ((MODE == 2) ? Wout[tid] : 0.f);
        if (MODE == 0) CXs[tid] = g_cX[tid];
        if (MODE == 2) WLO[tid] = g_wlo[tid];
        if (MODE == 2 && tid == 0) AUX[0] = g_aux[0];
    }
    float A1 = 0.f, a2 = 0.f, a3 = 0.f, a4 = 0.f, h = 0.f;
    float b4 = 0.f, A2n = 0.f, s = 0.f;
    if (tid < 64) {
        A1 = expf(-expf(nu_log[tid]));
        a2 = A1 * A1; a3 = a2 * A1; a4 = a2 * a2;
        h = carr[bc * 64 + tid];
        if (MODE != 2) {
            A2n = expf(-expf(nu_nx[tid]));
            float t2 = A2n * A2n; b4 = t2 * t2;
        }
    }
    cpwait();
    __syncthreads();

    for (int tl = 0; tl < NTIL; tl++) {
        __syncthreads();   // #1
        const size_t toff = ((size_t)bc * NTIL + tl) * TFL;
        const long tokb = tokbase + (long)tl * TILE;

        if (MODE == 0) {
            XS[tid] = xin[tokb + tid];
            XS[tid + 128] = xin[tokb + 128 + tid];
            __syncthreads();
#pragma unroll
            for (int it = 0; it < 32; it++) {
                int idx = it * 512 + tid * 4;
                int t = idx >> 6, n = idx & 63;
                float xv = XS[t];
                float4 c = *(const float4*)(CXs + n);
                *(float4*)(BUF + t * PBN + n) =
                    make_float4(xv * c.x, xv * c.y, xv * c.z, xv * c.w);
            }
        } else {
#pragma unroll
            for (int j = 0; j < 32; j++) {
                const int nt = j >> 2, mt = j & 3;
                float4 v = *(const float4*)(bu + fragoff(toff, w, j, lane));
                const int r0 = rb0 + 16 * mt + lq;
                const int nc = nt * 8 + 2 * kcol;
                *(ull*)(BUF + r0 * PBN + nc) = pk(v.x, v.y);
                *(ull*)(BUF + (r0 + 8) * PBN + nc) = pk(v.z, v.w);
            }
        }
        __syncthreads();   // #2

        // quad-Horner scan over [t][n] columns: BUF <- hprev (256 rows)
        if (tid < 64) {
            float* p = BUF + tid;
#pragma unroll 4
            for (int q = 0; q < 64; q++) {
                float* r = p + 4 * q * PBN;
                float v0 = r[0], v1 = r[PBN], v2 = r[2 * PBN], v3 = r[3 * PBN];
                float p2 = fmaf(A1, v0, v1);
                float p3 = fmaf(A1, p2, v2);
                float p4 = fmaf(A1, p3, v3);
                r[0] = h;
                r[PBN] = fmaf(A1, h, v0);
                r[2 * PBN] = fmaf(a2, h, p2);
                r[3 * PBN] = fmaf(a3, h, p3);
                h = fmaf(a4, h, p4);
            }
        }
        __syncthreads();   // #3

        // GEMM1: y = hprev @ Cm^T ; prefetch wtW
        if (MODE != 2) stage16k(wS0 + (cur ^ 1) * 16384, wtW, tid);
        float acc[8][16];
#pragma unroll
        for (int nt = 0; nt < 8; nt++)
#pragma unroll
            for (int j = 0; j < 16; j++) acc[nt][j] = 0.f;
        gemm_mma(BUF, WSL + cur * 4096, rb0, lq, kcol, lane, acc);

        // epilogue1: z = tanh~(y + Dv*u); MODE2 also folds output reduction
        float part[4][2];
        if (MODE == 2) {
#pragma unroll
            for (int mt = 0; mt < 4; mt++) { part[mt][0] = 0.f; part[mt][1] = 0.f; }
        }
#pragma unroll
        for (int nt = 0; nt < 8; nt++) {
            const int nc = nt * 8 + 2 * kcol;
            const ull dv2 = *(const ull*)(DVs + nc);
#pragma unroll
            for (int mt = 0; mt < 4; mt++) {
                ull u0, u1;
                float4 uu;
                if (MODE == 0) {
                    const int r0 = rb0 + 16 * mt + lq;
                    const ull w2 = *(const ull*)(W2s + nc);
                    u0 = mul2(dup2(XS[r0]), w2);
                    u1 = mul2(dup2(XS[r0 + 8]), w2);
                } else {
                    uu = *(const float4*)(uin + fragoff(toff, w, nt * 4 + mt, lane));
                    u0 = pk(uu.x, uu.y);
                    u1 = pk(uu.z, uu.w);
                }
                ull y0 = pk(acc[nt][4 * mt], acc[nt][4 * mt + 1]);
                ull y1 = pk(acc[nt][4 * mt + 2], acc[nt][4 * mt + 3]);
                fma2(y0, dv2, u0);
                fma2(y1, dv2, u1);
                float2 f0 = unp(y0), f1 = unp(y1);
                f0.x = f0.x * rsqrtf(fmaf(f0.x, f0.x, 1.0f));
                f0.y = f0.y * rsqrtf(fmaf(f0.y, f0.y, 1.0f));
                f1.x = f1.x * rsqrtf(fmaf(f1.x, f1.x, 1.0f));
                f1.y = f1.y * rsqrtf(fmaf(f1.y, f1.y, 1.0f));
                acc[nt][4 * mt] = f0.x;     acc[nt][4 * mt + 1] = f0.y;
                acc[nt][4 * mt + 2] = f1.x; acc[nt][4 * mt + 3] = f1.y;
                if (MODE == 2) {
                    const float2 wl = *(const float2*)(WLO + nc);
                    const float2 wo = *(const float2*)(W2s + nc);
                    part[mt][0] = fmaf(wl.x, f0.x, part[mt][0]);
                    part[mt][0] = fmaf(wl.y, f0.y, part[mt][0]);
                    part[mt][0] = fmaf(wo.x, uu.x, part[mt][0]);
                    part[mt][0] = fmaf(wo.y, uu.y, part[mt][0]);
                    part[mt][1] = fmaf(wl.x, f1.x, part[mt][1]);
                    part[mt][1] = fmaf(wl.y, f1.y, part[mt][1]);
                    part[mt][1] = fmaf(wo.x, uu.z, part[mt][1]);
                    part[mt][1] = fmaf(wo.y, uu.w, part[mt][1]);
                }
            }
        }

        if (MODE == 2) {
#pragma unroll
            for (int mt = 0; mt < 4; mt++)
#pragma unroll
                for (int hf = 0; hf < 2; hf++) {
                    float p = part[mt][hf];
                    p += __shfl_xor_sync(0xffffffffu, p, 1);
                    p += __shfl_xor_sync(0xffffffffu, p, 2);
                    if (kcol == 0)
                        uout[tokb + rb0 + 16 * mt + lq + 8 * hf] = AUX[0] + p;
                }
            continue;
        }

        cpwait();
        __syncthreads();   // #4
        stile_mma(BUF, rb0, lq, kcol, acc);   // BUF <- z
        __syncthreads();   // #5
        cur ^= 1;

        // GEMM2: o = z @ Wl^T + bl + u ; prefetch wtB
        stage16k(wS0 + (cur ^ 1) * 16384, wtB, tid);
#pragma unroll
        for (int nt = 0; nt < 8; nt++)
#pragma unroll
            for (int j = 0; j < 16; j++) acc[nt][j] = 0.f;
        gemm_mma(BUF, WSL + cur * 4096, rb0, lq, kcol, lane, acc);
#pragma unroll
        for (int nt = 0; nt < 8; nt++) {
            const int nc = nt * 8 + 2 * kcol;
            const ull bl2 = *(const ull*)(BLs + nc);
#pragma unroll
            for (int mt = 0; mt < 4; mt++) {
                ull u0, u1;
                if (MODE == 0) {
                    const int r0 = rb0 + 16 * mt + lq;
                    const ull w2 = *(const ull*)(W2s + nc);
                    u0 = mul2(dup2(XS[r0]), w2);
                    u1 = mul2(dup2(XS[r0 + 8]), w2);
                } else {
                    float4 uu = *(const float4*)(uin +
                                                 fragoff(toff, w, nt * 4 + mt, lane));
                    u0 = pk(uu.x, uu.y);
                    u1 = pk(uu.z, uu.w);
                }
                ull y0 = pk(acc[nt][4 * mt], acc[nt][4 * mt + 1]);
                ull y1 = pk(acc[nt][4 * mt + 2], acc[nt][4 * mt + 3]);
                y0 = add2(y0, add2(u0, bl2));
                y1 = add2(y1, add2(u1, bl2));
                float2 f0 = unp(y0), f1 = unp(y1);
                acc[nt][4 * mt] = f0.x;     acc[nt][4 * mt + 1] = f0.y;
                acc[nt][4 * mt + 2] = f1.x; acc[nt][4 * mt + 3] = f1.y;
                *(float4*)(uout + fragoff(toff, w, nt * 4 + mt, lane)) =
                    make_float4(f0.x, f0.y, f1.x, f1.y);
            }
        }
        cpwait();
        __syncthreads();   // #6
        stile_mma(BUF, rb0, lq, kcol, acc);   // BUF <- u_next
        __syncthreads();   // #7
        cur ^= 1;

        // GEMM3: Bu_next = u_next @ (g*Bm)^T ; prefetch next wtC
        stage16k(wS0 + (cur ^ 1) * 16384, wtC, tid);
#pragma unroll
        for (int nt = 0; nt < 8; nt++)
#pragma unroll
            for (int j = 0; j < 16; j++) acc[nt][j] = 0.f;
        gemm_mma(BUF, WSL + cur * 4096, rb0, lq, kcol, lane, acc);
#pragma unroll
        for (int nt = 0; nt < 8; nt++)
#pragma unroll
            for (int mt = 0; mt < 4; mt++)
                *(float4*)(bu + fragoff(toff, w, nt * 4 + mt, lane)) =
                    make_float4(acc[nt][4 * mt], acc[nt][4 * mt + 1],
                                acc[nt][4 * mt + 2], acc[nt][4 * mt + 3]);
        cpwait();
        __syncthreads();   // #8
        stile_mma(BUF, rb0, lq, kcol, acc);   // BUF <- Bu_next
        __syncthreads();   // #9
        cur ^= 1;

        // chunk end-state for next layer (quad-Horner over columns, 256 rows)
        if (tid < 64) {
            const float* p = BUF + tid;
#pragma unroll 4
            for (int q = 0; q < 64; q++) {
                const float* r = p + 4 * q * PBN;
                float p2 = fmaf(A2n, r[0], r[PBN]);
                float p3 = fmaf(A2n, p2, r[2 * PBN]);
                float p4 = fmaf(A2n, p3, r[3 * PBN]);
                s = fmaf(b4, s, p4);
            }
        }
    }
    if (MODE != 2 && tid < 64) ends[bc * 64 + tid] = s;
}

// ---------------------------------------------------------------------------
extern "C" void kernel_launch(void* const* d_in, const int* in_sizes, int n_in,
                              void* d_out, int out_size) {
    (void)in_sizes; (void)n_in; (void)out_size;
    const float* x   = (const float*)d_in[0];
    const float* Win = (const float*)d_in[1];
    const float* nu  = (const float*)d_in[2];
    const float* ga  = (const float*)d_in[3];
    const float* Bm  = (const float*)d_in[4];
    const float* Cm  = (const float*)d_in[5];
    const float* Dv  = (const float*)d_in[6];
    const float* Wl  = (const float*)d_in[7];
    const float* bl  = (const float*)d_in[8];
    const float* Wo  = (const float*)d_in[9];
    float* out = (float*)d_out;

    float *u, *bu, *ends, *carr, *wT;
    cudaGetSymbolAddress((void**)&u, g_u);
    cudaGetSymbolAddress((void**)&bu, g_bu);
    cudaGetSymbolAddress((void**)&ends, g_ends);
    cudaGetSymbolAddress((void**)&carr, g_carr);
    cudaGetSymbolAddress((void**)&wT, g_wT);

    static int inited = 0;
    if (!inited) {
        cudaFuncSetAttribute(k_apply<0,0>, cudaFuncAttributeMaxDynamicSharedMemorySize, SMEMB);
        cudaFuncSetAttribute(k_apply<1,1>, cudaFuncAttributeMaxDynamicSharedMemorySize, SMEMB);
        cudaFuncSetAttribute(k_apply<1,0>, cudaFuncAttributeMaxDynamicSharedMemorySize, SMEMB);
        cudaFuncSetAttribute(k_apply<2,1>, cudaFuncAttributeMaxDynamicSharedMemorySize, SMEMB);
        inited = 1;
    }

    const dim3 grid(B_ * CHUNKS), blk(128);

    k_prep<<<13, 128>>>(Cm, Wl, Bm, ga, Win, bl, Wo);
    k_init<<<grid, blk>>>(x, ends, nu);
    k_combine<<<B_, 128>>>(ends, carr, nu);
    k_apply<0,0><<<grid, blk, SMEMB>>>(x, u, u, bu, carr, ends,
                                       wT + 0 * HH, wT + 1 * HH, wT + 2 * HH,
                                       Dv, bl, nu, Win, Wo, nu + 64);
    k_combine<<<B_, 128>>>(ends, carr, nu + 64);
    k_apply<1,1><<<grid, blk, SMEMB>>>(x, u, u, bu, carr, ends,
                                       wT + 3 * HH, wT + 4 * HH, wT + 5 * HH,
                                       Dv + 64, bl + 64, nu + 64, Win, Wo,
                                       nu + 128);
    k_combine<<<B_, 128>>>(ends, carr, nu + 128);
    k_apply<1,0><<<grid, blk, SMEMB>>>(x, u, u, bu, carr, ends,
                                       wT + 6 * HH, wT + 7 * HH, wT + 8 * HH,
                                       Dv + 128, bl + 128, nu + 128, Win, Wo,
                                       nu + 192);
    k_combine<<<B_, 128>>>(ends, carr, nu + 192);
    k_apply<2,1><<<grid, blk, SMEMB>>>(x, u, out, bu, carr, ends,
                                       wT + 9 * HH, wT + 9 * HH, wT + 9 * HH,
                                       Dv + 192, bl + 192, nu + 192, Win, Wo,
                                       nu);
}

// round 14
// speedup vs baseline: 1.1708x; 1.1708x over previous
#include <cuda_runtime.h>
#include <cstdint>

#define B_     16
#define T_     65536
#define CHUNKS 128
#define TILE   128
#define NTIL   4
#define L_     512
#define PBN    76
#define HH     4096
typedef unsigned long long ull;
typedef unsigned int u32;

__device__ float g_u [(size_t)B_ * T_ * 64];
__device__ float g_bu[(size_t)B_ * T_ * 64];
__device__ float g_ends[B_ * CHUNKS * 64];
__device__ float g_carr[B_ * CHUNKS * 64];
__device__ float g_cX[64];
__device__ float g_wlo[64];
__device__ float g_aux[1];
__device__ float g_wT[12 * HH];   // fragment-packed tf32 weights (uint4 pairs)

__device__ __forceinline__ void fma2(ull& d, ull a, ull b) {
    asm("fma.rn.f32x2 %0, %1, %2, %0;" : "+l"(d) : "l"(a), "l"(b));
}
__device__ __forceinline__ ull add2(ull a, ull b) {
    ull d; asm("add.rn.f32x2 %0, %1, %2;" : "=l"(d) : "l"(a), "l"(b)); return d;
}
__device__ __forceinline__ ull mul2(ull a, ull b) {
    ull d; asm("mul.rn.f32x2 %0, %1, %2;" : "=l"(d) : "l"(a), "l"(b)); return d;
}
__device__ __forceinline__ ull dup2(float x) {
    ull r; asm("mov.b64 %0, {%1, %1};" : "=l"(r) : "f"(x)); return r;
}
__device__ __forceinline__ float2 unp(ull p) {
    float2 r; asm("mov.b64 {%0, %1}, %2;" : "=f"(r.x), "=f"(r.y) : "l"(p)); return r;
}
__device__ __forceinline__ ull pk(float a, float b) {
    ull r; asm("mov.b64 %0, {%1, %2};" : "=l"(r) : "f"(a), "f"(b)); return r;
}
__device__ __forceinline__ u32 cvt_tf32(float x) {
    u32 r; asm("cvt.rna.tf32.f32 %0, %1;" : "=r"(r) : "f"(x)); return r;
}
__device__ __forceinline__ void mma_tf32(float* d, u32 a0, u32 a1, u32 a2,
                                         u32 a3, u32 b0, u32 b1) {
    asm volatile(
        "mma.sync.aligned.m16n8k8.row.col.f32.tf32.tf32.f32 "
        "{%0,%1,%2,%3}, {%4,%5,%6,%7}, {%8,%9}, {%0,%1,%2,%3};"
        : "+f"(d[0]), "+f"(d[1]), "+f"(d[2]), "+f"(d[3])
        : "r"(a0), "r"(a1), "r"(a2), "r"(a3), "r"(b0), "r"(b1));
}

// weight staging: L2->smem (cg bypasses L1; keeps hot GEMM lines resident)
__device__ __forceinline__ void stage16k(u32 dst, const float* __restrict__ src,
                                         int tid) {
#pragma unroll
    for (int j = 0; j < 8; j++) {
        asm volatile("cp.async.cg.shared.global [%0], [%1], 16;"
                     :: "r"(dst + tid * 16 + j * 2048),
                        "l"(src + tid * 4 + j * 512));
    }
    asm volatile("cp.async.commit_group;");
}
__device__ __forceinline__ void cpwait() {
    asm volatile("cp.async.wait_group 0;");
}

// fragment-layout gmem offset
__device__ __forceinline__ size_t fragoff(size_t toff, int w, int j, int lane) {
    return toff + (size_t)w * 2048 + (size_t)(j * 32 + lane) * 4;
}

// GEMM1: A from BUF [t][n] pitch 76; B frags uint4-packed (2 nt per load)
__device__ __forceinline__ void gemm_mma(const float* __restrict__ BUF,
                                         const float* __restrict__ wt,
                                         int tb0, int lq, int kcol, int lane,
                                         float acc[8][8]) {
#pragma unroll
    for (int s = 0; s < 8; s++) {
        const int kb = s * 8;
        u32 a[2][4];
#pragma unroll
        for (int mt = 0; mt < 2; mt++) {
            const float* p = BUF + (tb0 + 16 * mt + lq) * PBN + kb + kcol;
            a[mt][0] = cvt_tf32(p[0]);
            a[mt][1] = cvt_tf32(p[8 * PBN]);
            a[mt][2] = cvt_tf32(p[4]);
            a[mt][3] = cvt_tf32(p[8 * PBN + 4]);
        }
        const uint4* wp = (const uint4*)(wt + s * 512) + lane;
#pragma unroll
        for (int np = 0; np < 4; np++) {
            uint4 b2 = wp[np * 32];
            const int nt0 = 2 * np, nt1 = 2 * np + 1;
            mma_tf32(&acc[nt0][0], a[0][0], a[0][1], a[0][2], a[0][3], b2.x, b2.y);
            mma_tf32(&acc[nt0][4], a[1][0], a[1][1], a[1][2], a[1][3], b2.x, b2.y);
            mma_tf32(&acc[nt1][0], a[0][0], a[0][1], a[0][2], a[0][3], b2.z, b2.w);
            mma_tf32(&acc[nt1][4], a[1][0], a[1][1], a[1][2], a[1][3], b2.z, b2.w);
        }
    }
}

// GEMM with A sourced from previous GEMM's D-fragments via intra-quad shfl.
__device__ __forceinline__ void gemm_frA(const float src[8][8],
                                         const float* __restrict__ wt,
                                         int lq, int kcol, int lane,
                                         float out[8][8]) {
    const bool par = (kcol & 1) != 0;
    const int src1 = (lq << 2) | (kcol >> 1);
    const int src2 = src1 + 2;
#pragma unroll
    for (int s = 0; s < 8; s++) {
        u32 a[2][4];
#pragma unroll
        for (int mt = 0; mt < 2; mt++) {
            float t0 = __shfl_sync(0xffffffffu, src[s][4 * mt + 0], src1);
            float t1 = __shfl_sync(0xffffffffu, src[s][4 * mt + 1], src1);
            float t2 = __shfl_sync(0xffffffffu, src[s][4 * mt + 2], src1);
            float t3 = __shfl_sync(0xffffffffu, src[s][4 * mt + 3], src1);
            float u0 = __shfl_sync(0xffffffffu, src[s][4 * mt + 0], src2);
            float u1 = __shfl_sync(0xffffffffu, src[s][4 * mt + 1], src2);
            float u2 = __shfl_sync(0xffffffffu, src[s][4 * mt + 2], src2);
            float u3 = __shfl_sync(0xffffffffu, src[s][4 * mt + 3], src2);
            a[mt][0] = cvt_tf32(par ? t1 : t0);
            a[mt][1] = cvt_tf32(par ? t3 : t2);
            a[mt][2] = cvt_tf32(par ? u1 : u0);
            a[mt][3] = cvt_tf32(par ? u3 : u2);
        }
        const uint4* wp = (const uint4*)(wt + s * 512) + lane;
#pragma unroll
        for (int np = 0; np < 4; np++) {
            uint4 b2 = wp[np * 32];
            const int nt0 = 2 * np, nt1 = 2 * np + 1;
            mma_tf32(&out[nt0][0], a[0][0], a[0][1], a[0][2], a[0][3], b2.x, b2.y);
            mma_tf32(&out[nt0][4], a[1][0], a[1][1], a[1][2], a[1][3], b2.x, b2.y);
            mma_tf32(&out[nt1][0], a[0][0], a[0][1], a[0][2], a[0][3], b2.z, b2.w);
            mma_tf32(&out[nt1][4], a[1][0], a[1][1], a[1][2], a[1][3], b2.z, b2.w);
        }
    }
}

// store D fragments into BUF [t][n]
__device__ __forceinline__ void stile_mma(float* __restrict__ BUF, int tb0,
                                          int lq, int kcol,
                                          const float acc[8][8]) {
#pragma unroll
    for (int nt = 0; nt < 8; nt++) {
        const int nc = nt * 8 + 2 * kcol;
#pragma unroll
        for (int mt = 0; mt < 2; mt++) {
            const int r0 = tb0 + 16 * mt + lq;
            *(ull*)(BUF + r0 * PBN + nc) = pk(acc[nt][4 * mt], acc[nt][4 * mt + 1]);
            *(ull*)(BUF + (r0 + 8) * PBN + nc) =
                pk(acc[nt][4 * mt + 2], acc[nt][4 * mt + 3]);
        }
    }
}

// ---------------------------------------------------------------------------
// k_prep: pack weights as uint4 B-fragment pairs.
// float index = s*512 + np*128 + lane*4 + c4, with
// nt = 2*np + (c4>>1), c = c4&1, n = nt*8 + lane/4, k = s*8 + (lane&3) + 4c.
// ---------------------------------------------------------------------------
__global__ void __launch_bounds__(128)
k_prep(const float* __restrict__ Cm, const float* __restrict__ Wl,
       const float* __restrict__ Bm, const float* __restrict__ ga,
       const float* __restrict__ Win, const float* __restrict__ bl,
       const float* __restrict__ Wout) {
    const int b = blockIdx.x;
    const int tid = threadIdx.x;
    if (b == 12) {
        if (tid < 64) {
            const int n = tid;
            float a = 0.f;
#pragma unroll
            for (int k = 0; k < 64; k++) a = fmaf(Bm[n * 64 + k], Win[k], a);
            g_cX[n] = expf(ga[n]) * a;
            float w = 0.f;
#pragma unroll
            for (int j = 0; j < 64; j++)
                w = fmaf(Wout[j], Wl[3 * HH + j * 64 + n], w);
            g_wlo[n] = w;
            if (n == 0) {
                float s = 0.f;
#pragma unroll
                for (int j = 0; j < 64; j++) s = fmaf(Wout[j], bl[192 + j], s);
                g_aux[0] = s;
            }
        }
        return;
    }
    const int l = b / 3, m = b % 3;
    if (m == 2 && l == 3) return;
    __shared__ float gam[64];
    const float* src = (m == 0) ? Cm + l * HH
                     : (m == 1) ? Wl + l * HH
                                : Bm + (l + 1) * HH;
    u32* dst = (u32*)(g_wT + b * HH);
    if (m == 2) {
        if (tid < 64) gam[tid] = expf(ga[(l + 1) * 64 + tid]);
        __syncthreads();
    }
    for (int idx = tid; idx < HH; idx += 128) {
        const int c4 = idx & 3, lane = (idx >> 2) & 31;
        const int np = (idx >> 7) & 3, s = idx >> 9;
        const int nt = 2 * np + (c4 >> 1);
        const int c = c4 & 1;
        const int n = nt * 8 + (lane >> 2);
        const int k = s * 8 + (lane & 3) + 4 * c;
        float v = src[n * 64 + k];
        if (m == 2) v *= gam[n];
        dst[idx] = cvt_tf32(v);
    }
}

__global__ void __launch_bounds__(128)
k_init(const float* __restrict__ x, float* __restrict__ ends,
       const float* __restrict__ nu_log) {
    __shared__ __align__(16) float xs[TILE];
    const int tid = threadIdx.x;
    const int bc = blockIdx.x;
    const long tokbase = (long)(bc / CHUNKS) * T_ + (long)(bc % CHUNKS) * L_;

    float A = 0.f, a4 = 0.f, s = 0.f;
    if (tid < 64) {
        A = expf(-expf(nu_log[tid]));
        float a2 = A * A; a4 = a2 * a2;
    }
    for (int tl = 0; tl < NTIL; tl++) {
        __syncthreads();
        xs[tid] = x[tokbase + tl * TILE + tid];
        __syncthreads();
        if (tid < 64) {
#pragma unroll 8
            for (int q = 0; q < 32; q++) {
                float4 v = *(const float4*)(xs + 4 * q);
                float p2 = fmaf(A, v.x, v.y);
                float p3 = fmaf(A, p2, v.z);
                float p4 = fmaf(A, p3, v.w);
                s = fmaf(a4, s, p4);
            }
        }
    }
    if (tid < 64) ends[bc * 64 + tid] = g_cX[tid] * s;
}

__global__ void __launch_bounds__(128)
k_combine(const float* __restrict__ ends, float* __restrict__ carries,
          const float* __restrict__ nu_log) {
    __shared__ float es[CHUNKS * 64];
    const int b = blockIdx.x;
    const int tid = threadIdx.x;
    for (int i = tid; i < CHUNKS * 64; i += 128)
        es[i] = ends[b * CHUNKS * 64 + i];
    __syncthreads();
    if (tid < 64) {
        const int n = tid;
        const float AL = expf(-expf(nu_log[n]) * (float)L_);
        float carry = 0.f;
#pragma unroll 8
        for (int c = 0; c < CHUNKS; c++) {
            carries[(b * CHUNKS + c) * 64 + n] = carry;
            carry = fmaf(AL, carry, es[c * 64 + n]);
        }
    }
}

// ---------------------------------------------------------------------------
#define SM_BUF  0
#define SM_W    9728          // 2 slots x 4096 floats
#define SM_XS   17920
#define SM_DV   18048
#define SM_BL   18112
#define SM_W2   18176
#define SM_WLO  18240
#define SM_AUX  18304
#define SM_CX   18308
#define SMEMF   18376
#define SMEMB   (SMEMF * 4)

template <int MODE, int REV>
__global__ void __launch_bounds__(128, 3)
k_apply(const float* __restrict__ xin, const float* __restrict__ uin,
        float* __restrict__ uout, float* __restrict__ bu,
        const float* __restrict__ carr, float* __restrict__ ends,
        const float* __restrict__ wtC, const float* __restrict__ wtW,
        const float* __restrict__ wtB,
        const float* __restrict__ Dv, const float* __restrict__ bl,
        const float* __restrict__ nu_log, const float* __restrict__ Win,
        const float* __restrict__ Wout, const float* __restrict__ nu_nx) {
    extern __shared__ __align__(16) float sm[];
    float* BUF = sm + SM_BUF;
    float* WSL = sm + SM_W;
    float* XS  = sm + SM_XS;
    float* DVs = sm + SM_DV;
    float* BLs = sm + SM_BL;
    float* W2s = sm + SM_W2;
    float* WLO = sm + SM_WLO;
    float* AUX = sm + SM_AUX;
    float* CXs = sm + SM_CX;

    const int tid = threadIdx.x;
    const int lane = tid & 31;
    const int lq = lane >> 2, kcol = lane & 3;
    const int w = tid >> 5;
    const int tb0 = w * 32;
    const int bc = REV ? (int)(gridDim.x - 1 - blockIdx.x) : (int)blockIdx.x;
    const long tokbase = (long)(bc / CHUNKS) * T_ + (long)(bc % CHUNKS) * L_;
    const u32 wS0 = (u32)__cvta_generic_to_shared(WSL);

    stage16k(wS0, wtC, tid);
    int cur = 0;

    if (tid < 64) {
        DVs[tid] = Dv[tid];
        BLs[tid] = bl[tid];
        W2s[tid] = (MODE == 0) ? Win[tid] : ((MODE == 2) ? Wout[tid] : 0.f);
        if (MODE == 0) CXs[tid] = g_cX[tid];
        if (MODE == 2) WLO[tid] = g_wlo[tid];
        if (MODE == 2 && tid == 0) AUX[0] = g_aux[0];
    }
    float A1 = 0.f, a2 = 0.f, a3 = 0.f, a4 = 0.f, h = 0.f;
    float b4 = 0.f, A2n = 0.f, s = 0.f;
    if (tid < 64) {
        A1 = expf(-expf(nu_log[tid]));
        a2 = A1 * A1; a3 = a2 * A1; a4 = a2 * a2;
        h = carr[bc * 64 + tid];
        if (MODE != 2) {
            A2n = expf(-expf(nu_nx[tid]));
            float t2 = A2n * A2n; b4 = t2 * t2;
        }
    }
    cpwait();
    __syncthreads();

    for (int tl = 0; tl < NTIL; tl++) {
        __syncthreads();   // #1: BUF safe vs prev ends-read; slot cur^1 free
        const size_t toff = ((size_t)bc * NTIL + tl) * (64 * TILE);
        const long tokb = tokbase + (long)tl * TILE;

        if (MODE == 0) {
            XS[tid] = xin[tokb + tid];
            __syncthreads();
#pragma unroll
            for (int it = 0; it < 16; it++) {
                int idx = it * 512 + tid * 4;
                int t = idx >> 6, n = idx & 63;
                float xv = XS[t];
                float4 c = *(const float4*)(CXs + n);
                *(float4*)(BUF + t * PBN + n) =
                    make_float4(xv * c.x, xv * c.y, xv * c.z, xv * c.w);
            }
        } else {
#pragma unroll
            for (int j = 0; j < 16; j++) {
                const int nt = j >> 1, mt = j & 1;
                float4 v = *(const float4*)(bu + fragoff(toff, w, j, lane));
                const int r0 = tb0 + 16 * mt + lq;
                const int nc = nt * 8 + 2 * kcol;
                *(ull*)(BUF + r0 * PBN + nc) = pk(v.x, v.y);
                *(ull*)(BUF + (r0 + 8) * PBN + nc) = pk(v.z, v.w);
            }
        }
        __syncthreads();   // #2

        // quad-Horner scan over [t][n] columns: BUF <- hprev
        if (tid < 64) {
            float* p = BUF + tid;
#pragma unroll 4
            for (int q = 0; q < 32; q++) {
                float* r = p + 4 * q * PBN;
                float v0 = r[0], v1 = r[PBN], v2 = r[2 * PBN], v3 = r[3 * PBN];
                float p2 = fmaf(A1, v0, v1);
                float p3 = fmaf(A1, p2, v2);
                float p4 = fmaf(A1, p3, v3);
                r[0] = h;
                r[PBN] = fmaf(A1, h, v0);
                r[2 * PBN] = fmaf(a2, h, p2);
                r[3 * PBN] = fmaf(a3, h, p3);
                h = fmaf(a4, h, p4);
            }
        }
        __syncthreads();   // #3

        // GEMM1: y = hprev @ Cm^T ; prefetch wtW into idle slot
        if (MODE != 2) stage16k(wS0 + (cur ^ 1) * 16384, wtW, tid);
        float acc[8][8];
#pragma unroll
        for (int nt = 0; nt < 8; nt++)
#pragma unroll
            for (int j = 0; j < 8; j++) acc[nt][j] = 0.f;
        gemm_mma(BUF, WSL + cur * 4096, tb0, lq, kcol, lane, acc);

        // epilogue1: z = tanh~(y + Dv*u)  (in place in acc)
#pragma unroll
        for (int nt = 0; nt < 8; nt++) {
            const int nc = nt * 8 + 2 * kcol;
            const ull dv2 = *(const ull*)(DVs + nc);
#pragma unroll
            for (int mt = 0; mt < 2; mt++) {
                ull u0, u1;
                if (MODE == 0) {
                    const int r0 = tb0 + 16 * mt + lq;
                    const ull w2 = *(const ull*)(W2s + nc);
                    u0 = mul2(dup2(XS[r0]), w2);
                    u1 = mul2(dup2(XS[r0 + 8]), w2);
                } else {
                    float4 uu = *(const float4*)(uin +
                                                 fragoff(toff, w, nt * 2 + mt, lane));
                    u0 = pk(uu.x, uu.y);
                    u1 = pk(uu.z, uu.w);
                }
                ull y0 = pk(acc[nt][4 * mt], acc[nt][4 * mt + 1]);
                ull y1 = pk(acc[nt][4 * mt + 2], acc[nt][4 * mt + 3]);
                fma2(y0, dv2, u0);
                fma2(y1, dv2, u1);
                float2 f0 = unp(y0), f1 = unp(y1);
                acc[nt][4 * mt]     = f0.x * rsqrtf(fmaf(f0.x, f0.x, 1.0f));
                acc[nt][4 * mt + 1] = f0.y * rsqrtf(fmaf(f0.y, f0.y, 1.0f));
                acc[nt][4 * mt + 2] = f1.x * rsqrtf(fmaf(f1.x, f1.x, 1.0f));
                acc[nt][4 * mt + 3] = f1.y * rsqrtf(fmaf(f1.y, f1.y, 1.0f));
            }
        }

        if (MODE == 2) {
            float part[2][2] = {{0.f, 0.f}, {0.f, 0.f}};
#pragma unroll
            for (int nt = 0; nt < 8; nt++) {
                const int nc = nt * 8 + 2 * kcol;
                const float2 wl = *(const float2*)(WLO + nc);
                const float2 wo = *(const float2*)(W2s + nc);
#pragma unroll
                for (int mt = 0; mt < 2; mt++) {
                    float4 uu = *(const float4*)(uin +
                                                 fragoff(toff, w, nt * 2 + mt, lane));
                    part[mt][0] = fmaf(wl.x, acc[nt][4 * mt], part[mt][0]);
                    part[mt][0] = fmaf(wl.y, acc[nt][4 * mt + 1], part[mt][0]);
                    part[mt][0] = fmaf(wo.x, uu.x, part[mt][0]);
                    part[mt][0] = fmaf(wo.y, uu.y, part[mt][0]);
                    part[mt][1] = fmaf(wl.x, acc[nt][4 * mt + 2], part[mt][1]);
                    part[mt][1] = fmaf(wl.y, acc[nt][4 * mt + 3], part[mt][1]);
                    part[mt][1] = fmaf(wo.x, uu.z, part[mt][1]);
                    part[mt][1] = fmaf(wo.y, uu.w, part[mt][1]);
                }
            }
#pragma unroll
            for (int mt = 0; mt < 2; mt++)
#pragma unroll
                for (int hf = 0; hf < 2; hf++) {
                    float p = part[mt][hf];
                    p += __shfl_xor_sync(0xffffffffu, p, 1);
                    p += __shfl_xor_sync(0xffffffffu, p, 2);
                    if (kcol == 0)
                        uout[tokb + tb0 + 16 * mt + lq + 8 * hf] = AUX[0] + p;
                }
            continue;
        }

        cpwait();
        __syncthreads();   // #4: wtW staged; GEMM1 done with slot cur

        // GEMM2: o = z @ Wl^T + bl + u ; A via shfl from acc; prefetch wtB
        stage16k(wS0 + cur * 16384, wtB, tid);
        float acc2[8][8];
#pragma unroll
        for (int nt = 0; nt < 8; nt++)
#pragma unroll
            for (int j = 0; j < 8; j++) acc2[nt][j] = 0.f;
        gemm_frA(acc, WSL + (cur ^ 1) * 4096, lq, kcol, lane, acc2);
#pragma unroll
        for (int nt = 0; nt < 8; nt++) {
            const int nc = nt * 8 + 2 * kcol;
            const ull bl2 = *(const ull*)(BLs + nc);
#pragma unroll
            for (int mt = 0; mt < 2; mt++) {
                ull u0, u1;
                if (MODE == 0) {
                    const int r0 = tb0 + 16 * mt + lq;
                    const ull w2 = *(const ull*)(W2s + nc);
                    u0 = mul2(dup2(XS[r0]), w2);
                    u1 = mul2(dup2(XS[r0 + 8]), w2);
                } else {
                    float4 uu = *(const float4*)(uin +
                                                 fragoff(toff, w, nt * 2 + mt, lane));
                    u0 = pk(uu.x, uu.y);
                    u1 = pk(uu.z, uu.w);
                }
                ull y0 = pk(acc2[nt][4 * mt], acc2[nt][4 * mt + 1]);
                ull y1 = pk(acc2[nt][4 * mt + 2], acc2[nt][4 * mt + 3]);
                y0 = add2(y0, add2(u0, bl2));
                y1 = add2(y1, add2(u1, bl2));
                float2 f0 = unp(y0), f1 = unp(y1);
                acc2[nt][4 * mt] = f0.x;     acc2[nt][4 * mt + 1] = f0.y;
                acc2[nt][4 * mt + 2] = f1.x; acc2[nt][4 * mt + 3] = f1.y;
                *(float4*)(uout + fragoff(toff, w, nt * 2 + mt, lane)) =
                    make_float4(f0.x, f0.y, f1.x, f1.y);
            }
        }
        cpwait();
        __syncthreads();   // #5: wtB staged; GEMM2 done with slot cur^1

        // GEMM3: Bu_next = u_next @ (g*Bm)^T ; A via shfl from acc2;
        // prefetch next tile's wtC into slot cur^1
        stage16k(wS0 + (cur ^ 1) * 16384, wtC, tid);
#pragma unroll
        for (int nt = 0; nt < 8; nt++)
#pragma unroll
            for (int j = 0; j < 8; j++) acc[nt][j] = 0.f;
        gemm_frA(acc2, WSL + cur * 4096, lq, kcol, lane, acc);
#pragma unroll
        for (int nt = 0; nt < 8; nt++)
#pragma unroll
            for (int mt = 0; mt < 2; mt++)
                *(float4*)(bu + fragoff(toff, w, nt * 2 + mt, lane)) =
                    make_float4(acc[nt][4 * mt], acc[nt][4 * mt + 1],
                                acc[nt][4 * mt + 2], acc[nt][4 * mt + 3]);
        stile_mma(BUF, tb0, lq, kcol, acc);   // BUF <- Bu_next (for ends)
        cpwait();
        __syncthreads();   // #6: stile visible; wtC staged

        // chunk end-state for next layer (quad-Horner over columns)
        if (tid < 64) {
            const float* p = BUF + tid;
#pragma unroll 4
            for (int q = 0; q < 32; q++) {
                const float* r = p + 4 * q * PBN;
                float p2 = fmaf(A2n, r[0], r[PBN]);
                float p3 = fmaf(A2n, p2, r[2 * PBN]);
                float p4 = fmaf(A2n, p3, r[3 * PBN]);
                s = fmaf(b4, s, p4);
            }
        }
        cur ^= 1;
    }
    if (MODE != 2 && tid < 64) ends[bc * 64 + tid] = s;
}

// ---------------------------------------------------------------------------
extern "C" void kernel_launch(void* const* d_in, const int* in_sizes, int n_in,
                              void* d_out, int out_size) {
    (void)in_sizes; (void)n_in; (void)out_size;
    const float* x   = (const float*)d_in[0];
    const float* Win = (const float*)d_in[1];
    const float* nu  = (const float*)d_in[2];
    const float* ga  = (const float*)d_in[3];
    const float* Bm  = (const float*)d_in[4];
    const float* Cm  = (const float*)d_in[5];
    const float* Dv  = (const float*)d_in[6];
    const float* Wl  = (const float*)d_in[7];
    const float* bl  = (const float*)d_in[8];
    const float* Wo  = (const float*)d_in[9];
    float* out = (float*)d_out;

    float *u, *bu, *ends, *carr, *wT;
    cudaGetSymbolAddress((void**)&u, g_u);
    cudaGetSymbolAddress((void**)&bu, g_bu);
    cudaGetSymbolAddress((void**)&ends, g_ends);
    cudaGetSymbolAddress((void**)&carr, g_carr);
    cudaGetSymbolAddress((void**)&wT, g_wT);

    static int inited = 0;
    if (!inited) {
        cudaFuncSetAttribute(k_apply<0,0>, cudaFuncAttributeMaxDynamicSharedMemorySize, SMEMB);
        cudaFuncSetAttribute(k_apply<1,1>, cudaFuncAttributeMaxDynamicSharedMemorySize, SMEMB);
        cudaFuncSetAttribute(k_apply<1,0>, cudaFuncAttributeMaxDynamicSharedMemorySize, SMEMB);
        cudaFuncSetAttribute(k_apply<2,1>, cudaFuncAttributeMaxDynamicSharedMemorySize, SMEMB);
        inited = 1;
    }

    const dim3 grid(B_ * CHUNKS), blk(128);

    k_prep<<<13, 128>>>(Cm, Wl, Bm, ga, Win, bl, Wo);
    k_init<<<grid, blk>>>(x, ends, nu);
    k_combine<<<B_, 128>>>(ends, carr, nu);
    k_apply<0,0><<<grid, blk, SMEMB>>>(x, u, u, bu, carr, ends,
                                       wT + 0 * HH, wT + 1 * HH, wT + 2 * HH,
                                       Dv, bl, nu, Win, Wo, nu + 64);
    k_combine<<<B_, 128>>>(ends, carr, nu + 64);
    k_apply<1,1><<<grid, blk, SMEMB>>>(x, u, u, bu, carr, ends,
                                       wT + 3 * HH, wT + 4 * HH, wT + 5 * HH,
                                       Dv + 64, bl + 64, nu + 64, Win, Wo,
                                       nu + 128);
    k_combine<<<B_, 128>>>(ends, carr, nu + 128);
    k_apply<1,0><<<grid, blk, SMEMB>>>(x, u, u, bu, carr, ends,
                                       wT + 6 * HH, wT + 7 * HH, wT + 8 * HH,
                                       Dv + 128, bl + 128, nu + 128, Win, Wo,
                                       nu + 192);
    k_combine<<<B_, 128>>>(ends, carr, nu + 192);
    k_apply<2,1><<<grid, blk, SMEMB>>>(x, u, out, bu, carr, ends,
                                       wT + 9 * HH, wT + 9 * HH, wT + 9 * HH,
                                       Dv + 192, bl + 192, nu + 192, Win, Wo,
                                       nu);
}